// round 3
// baseline (speedup 1.0000x reference)
#include <cuda_runtime.h>
#include <cuda_bf16.h>
#include <math.h>

// Problem constants (validated against in_sizes at launch)
#define MAXN 50000
#define MAXE 400000
#define DD   128
#define LL   5
#define BN_EPS 1e-5f

// ---------------- static device scratch (no allocations allowed) -------------
__device__ float g_bufA[(size_t)MAXN * DD];
__device__ float g_bufB[(size_t)MAXN * DD];
__device__ float g_h2  [(size_t)MAXN * DD];
__device__ float g_agg [(size_t)MAXN * DD];
__device__ float g_norm[MAXE];
__device__ float g_deg [MAXN];
__device__ float g_stats[2 * DD];
__device__ float g_scale[DD];
__device__ float g_shift[DD];

// ---------------- graph norm ------------------------------------------------
__global__ void deg_kernel(const int* __restrict__ col, float* __restrict__ deg, int E) {
    int e = blockIdx.x * blockDim.x + threadIdx.x;
    if (e < E) atomicAdd(&deg[col[e]], 1.0f);
}

__global__ void dinv_kernel(float* __restrict__ deg, int N) {
    int i = blockIdx.x * blockDim.x + threadIdx.x;
    if (i < N) {
        float d = deg[i];
        deg[i] = (d > 0.0f) ? rsqrtf(d) : 0.0f;
    }
}

__global__ void norm_kernel(const int* __restrict__ row, const int* __restrict__ col,
                            const float* __restrict__ dinv, float* __restrict__ nrm, int E) {
    int e = blockIdx.x * blockDim.x + threadIdx.x;
    if (e < E) nrm[e] = dinv[row[e]] * dinv[col[e]];
}

// ---------------- edge message + scatter-add --------------------------------
// One warp per edge; lane handles 4 consecutive features (float4).
// msg = norm[e] * (h[row[e]] + ea0*W1r0 + ea1*W1r1 + ea2*W1r2 + ea3*W2)
// agg[col[e]] += msg   via red.global.add.v4.f32 (one vector reduction per lane)
__global__ __launch_bounds__(256) void edge_msg_kernel(
    const float* __restrict__ h, const int* __restrict__ rowi, const int* __restrict__ coli,
    const float* __restrict__ ea, const float* __restrict__ nrm,
    const float* __restrict__ W1l, const float* __restrict__ W2l,
    float* __restrict__ agg, int E)
{
    __shared__ float4 w0[32], w1[32], w2[32], w3[32];
    int t = threadIdx.x;
    if (t < 32) {
        w0[t] = ((const float4*)(W1l      ))[t];
        w1[t] = ((const float4*)(W1l + 128))[t];
        w2[t] = ((const float4*)(W1l + 256))[t];
        w3[t] = ((const float4*)(W2l      ))[t];
    }
    __syncthreads();

    int e = blockIdx.x * 8 + (t >> 5);
    if (e >= E) return;
    int lane = t & 31;

    int r = rowi[e];
    int c = coli[e];
    float nr = nrm[e];
    float4 a = ((const float4*)ea)[e];            // [E,4] row-major

    float4 hv = ((const float4*)(h + (size_t)r * DD))[lane];
    float4 q0 = w0[lane], q1 = w1[lane], q2 = w2[lane], q3 = w3[lane];

    float4 m;
    m.x = nr * (hv.x + a.x * q0.x + a.y * q1.x + a.z * q2.x + a.w * q3.x);
    m.y = nr * (hv.y + a.x * q0.y + a.y * q1.y + a.z * q2.y + a.w * q3.y);
    m.z = nr * (hv.z + a.x * q0.z + a.y * q1.z + a.z * q2.z + a.w * q3.z);
    m.w = nr * (hv.w + a.x * q0.w + a.y * q1.w + a.z * q2.w + a.w * q3.w);

    float* dst = agg + (size_t)c * DD + lane * 4;
    asm volatile("red.global.add.v4.f32 [%0], {%1, %2, %3, %4};"
                 :: "l"(dst), "f"(m.x), "f"(m.y), "f"(m.z), "f"(m.w) : "memory");
}

// ---------------- fused GEMM + bias + ReLU + BN stats -----------------------
// h2[m][n] = relu( sum_k hin[m][k]*Wm[n][k] + sum_k agg[m][k]*Wm[n][128+k] + bm[n] )
// Also accumulates per-feature sum and sum-of-squares into stats[0:128]/[128:256].
#define GBM 128
#define GBN 128
#define GBK 16
__global__ __launch_bounds__(256) void gemm_bn_kernel(
    const float* __restrict__ hin, const float* __restrict__ agg,
    const float* __restrict__ Wml,   // [128][256] row-major
    const float* __restrict__ bml,   // [128]
    float* __restrict__ h2, float* __restrict__ stats, int M)
{
    __shared__ float As[GBK][GBM];
    __shared__ float Bs[GBK][GBN];

    int tid = threadIdx.x;
    int tx = tid & 15;          // output-col group
    int ty = tid >> 4;          // output-row group
    int m0 = blockIdx.x * GBM;

    float acc[8][8];
#pragma unroll
    for (int i = 0; i < 8; i++)
#pragma unroll
        for (int j = 0; j < 8; j++) acc[i][j] = 0.0f;

#pragma unroll 1
    for (int kt = 0; kt < 256 / GBK; ++kt) {
        int k0 = kt * GBK;
        const float* src = (k0 < 128) ? hin : agg;
        int ksrc = (k0 < 128) ? k0 : (k0 - 128);

        // A tile: 128 rows x 16 k, loaded as float4 along k, stored transposed
#pragma unroll
        for (int r = 0; r < 2; ++r) {
            int id = tid + r * 256;
            int m = id >> 2;
            int kq = (id & 3) * 4;
            int mg = m0 + m;
            float4 v = make_float4(0.f, 0.f, 0.f, 0.f);
            if (mg < M) v = *(const float4*)(src + (size_t)mg * DD + ksrc + kq);
            As[kq + 0][m] = v.x; As[kq + 1][m] = v.y;
            As[kq + 2][m] = v.z; As[kq + 3][m] = v.w;
        }
        // B tile: Bs[k][n] = Wm[n][k]
#pragma unroll
        for (int r = 0; r < 2; ++r) {
            int id = tid + r * 256;
            int n = id >> 2;
            int kq = (id & 3) * 4;
            float4 v = *(const float4*)(Wml + (size_t)n * 256 + k0 + kq);
            Bs[kq + 0][n] = v.x; Bs[kq + 1][n] = v.y;
            Bs[kq + 2][n] = v.z; Bs[kq + 3][n] = v.w;
        }
        __syncthreads();

#pragma unroll
        for (int kk = 0; kk < GBK; ++kk) {
            float a[8], b[8];
#pragma unroll
            for (int i = 0; i < 8; i++) a[i] = As[kk][ty * 8 + i];
#pragma unroll
            for (int j = 0; j < 8; j++) b[j] = Bs[kk][tx * 8 + j];
#pragma unroll
            for (int i = 0; i < 8; i++)
#pragma unroll
                for (int j = 0; j < 8; j++) acc[i][j] += a[i] * b[j];
        }
        __syncthreads();
    }

    // Epilogue: bias + ReLU + write + per-column stats
    float bias[8];
#pragma unroll
    for (int j = 0; j < 8; j++) bias[j] = bml[tx * 8 + j];

    float colsum[8], colsq[8];
#pragma unroll
    for (int j = 0; j < 8; j++) { colsum[j] = 0.f; colsq[j] = 0.f; }

#pragma unroll
    for (int i = 0; i < 8; i++) {
        int mg = m0 + ty * 8 + i;
        bool valid = (mg < M);
        float vals[8];
#pragma unroll
        for (int j = 0; j < 8; j++) {
            float v = fmaxf(acc[i][j] + bias[j], 0.0f);
            vals[j] = v;
            if (valid) { colsum[j] += v; colsq[j] += v * v; }
        }
        if (valid) {
            float* dst = h2 + (size_t)mg * DD + tx * 8;
            *(float4*)(dst)     = make_float4(vals[0], vals[1], vals[2], vals[3]);
            *(float4*)(dst + 4) = make_float4(vals[4], vals[5], vals[6], vals[7]);
        }
    }

    // Block-level stats reduction (reuse As: 16*128 floats)
    float* red = &As[0][0];
    __syncthreads();
#pragma unroll
    for (int j = 0; j < 8; j++) red[ty * 128 + tx * 8 + j] = colsum[j];
    __syncthreads();
    if (tid < 128) {
        float s = 0.f;
#pragma unroll
        for (int t2 = 0; t2 < 16; t2++) s += red[t2 * 128 + tid];
        atomicAdd(&stats[tid], s);
    }
    __syncthreads();
#pragma unroll
    for (int j = 0; j < 8; j++) red[ty * 128 + tx * 8 + j] = colsq[j];
    __syncthreads();
    if (tid < 128) {
        float s = 0.f;
#pragma unroll
        for (int t2 = 0; t2 < 16; t2++) s += red[t2 * 128 + tid];
        atomicAdd(&stats[128 + tid], s);
    }
}

// ---------------- BN finalize (compute per-feature scale/shift) -------------
__global__ void bn_finalize_kernel(const float* __restrict__ stats,
                                   const float* __restrict__ gamma_l,
                                   const float* __restrict__ beta_l,
                                   float* __restrict__ scale, float* __restrict__ shift,
                                   float invM)
{
    int d = threadIdx.x;
    float mean = stats[d] * invM;
    float var  = stats[DD + d] * invM - mean * mean;
    float inv  = rsqrtf(fmaxf(var, 0.0f) + BN_EPS);
    float sc   = gamma_l[d] * inv;
    scale[d] = sc;
    shift[d] = beta_l[d] - mean * sc;
}

// ---------------- BN apply (+ optional ReLU) --------------------------------
__global__ __launch_bounds__(256) void bn_apply_kernel(
    const float* __restrict__ h2, const float* __restrict__ scale,
    const float* __restrict__ shift, float* __restrict__ out,
    int total4, int relu)
{
    int i = blockIdx.x * blockDim.x + threadIdx.x;
    if (i >= total4) return;
    int d = (i * 4) & (DD - 1);
    float4 v  = ((const float4*)h2)[i];
    float4 sc = *(const float4*)(scale + d);
    float4 sh = *(const float4*)(shift + d);
    v.x = v.x * sc.x + sh.x;
    v.y = v.y * sc.y + sh.y;
    v.z = v.z * sc.z + sh.z;
    v.w = v.w * sc.w + sh.w;
    if (relu) {
        v.x = fmaxf(v.x, 0.f); v.y = fmaxf(v.y, 0.f);
        v.z = fmaxf(v.z, 0.f); v.w = fmaxf(v.w, 0.f);
    }
    ((float4*)out)[i] = v;
}

// ---------------- launch ----------------------------------------------------
extern "C" void kernel_launch(void* const* d_in, const int* in_sizes, int n_in,
                              void* d_out, int out_size)
{
    const float* x     = (const float*)d_in[0];
    const int*   ei    = (const int*)  d_in[1];
    const float* ea    = (const float*)d_in[2];
    const float* W1    = (const float*)d_in[3];
    const float* W2    = (const float*)d_in[4];
    const float* Wm    = (const float*)d_in[5];
    const float* bm    = (const float*)d_in[6];
    const float* gamma = (const float*)d_in[7];
    const float* beta  = (const float*)d_in[8];

    int N = in_sizes[0] / DD;
    int E = in_sizes[1] / 2;
    const int* rowi = ei;
    const int* coli = ei + E;

    float *bufA, *bufB, *h2, *agg, *nrm, *deg, *stats, *scale, *shift;
    cudaGetSymbolAddress((void**)&bufA,  g_bufA);
    cudaGetSymbolAddress((void**)&bufB,  g_bufB);
    cudaGetSymbolAddress((void**)&h2,    g_h2);
    cudaGetSymbolAddress((void**)&agg,   g_agg);
    cudaGetSymbolAddress((void**)&nrm,   g_norm);
    cudaGetSymbolAddress((void**)&deg,   g_deg);
    cudaGetSymbolAddress((void**)&stats, g_stats);
    cudaGetSymbolAddress((void**)&scale, g_scale);
    cudaGetSymbolAddress((void**)&shift, g_shift);

    // Graph normalization (once)
    cudaMemsetAsync(deg, 0, (size_t)N * sizeof(float));
    deg_kernel <<<(E + 255) / 256, 256>>>(coli, deg, E);
    dinv_kernel<<<(N + 255) / 256, 256>>>(deg, N);
    norm_kernel<<<(E + 255) / 256, 256>>>(rowi, coli, deg, nrm, E);

    const float* hin = x;
    float* outs[LL] = { bufA, bufB, bufA, bufB, (float*)d_out };

    for (int l = 0; l < LL; ++l) {
        cudaMemsetAsync(agg,   0, (size_t)N * DD * sizeof(float));
        cudaMemsetAsync(stats, 0, 2 * DD * sizeof(float));

        edge_msg_kernel<<<(E + 7) / 8, 256>>>(
            hin, rowi, coli, ea, nrm,
            W1 + (size_t)l * 3 * DD, W2 + (size_t)l * DD, agg, E);

        gemm_bn_kernel<<<(N + GBM - 1) / GBM, 256>>>(
            hin, agg, Wm + (size_t)l * DD * 2 * DD, bm + (size_t)l * DD,
            h2, stats, N);

        bn_finalize_kernel<<<1, DD>>>(
            stats, gamma + (size_t)l * DD, beta + (size_t)l * DD,
            scale, shift, 1.0f / (float)N);

        int total4 = N * (DD / 4);
        bn_apply_kernel<<<(total4 + 255) / 256, 256>>>(
            h2, scale, shift, outs[l], total4, (l < LL - 1) ? 1 : 0);

        hin = outs[l];
    }
}